// round 4
// baseline (speedup 1.0000x reference)
#include <cuda_runtime.h>
#include <cuda_bf16.h>
#include <cstdint>
#include <cstddef>

#define NTOK 4096
#define HDIM 1024
#define IDIM 4096
#define NEXP 8

typedef __nv_bfloat16 bf16;

// ------------------------- scratch (static device, no allocs) -------------------------
__device__ bf16 g_x_hi[(size_t)NTOK * HDIM];
__device__ bf16 g_x_lo[(size_t)NTOK * HDIM];
__device__ bf16 g_w1_hi[(size_t)NEXP * IDIM * HDIM];
__device__ bf16 g_w1_lo[(size_t)NEXP * IDIM * HDIM];
__device__ bf16 g_w2_hi[(size_t)NEXP * HDIM * IDIM];
__device__ bf16 g_w2_lo[(size_t)NEXP * HDIM * IDIM];
__device__ bf16 g_mid_hi[(size_t)NEXP * NTOK * IDIM];   // prob-scaled gelu output, hi
__device__ bf16 g_mid_lo[(size_t)NEXP * NTOK * IDIM];   // prob-scaled gelu output, lo
__device__ float g_probs[NTOK * NEXP];

// ------------------------- PTX helpers -------------------------
__device__ __forceinline__ uint32_t smem_u32(const void* p) {
    uint32_t a;
    asm("{ .reg .u64 t; cvta.to.shared.u64 t, %1; cvt.u32.u64 %0, t; }" : "=r"(a) : "l"(p));
    return a;
}

__device__ __forceinline__ void cp_async16(uint32_t smem, const void* g) {
    asm volatile("cp.async.cg.shared.global [%0], [%1], 16;\n" :: "r"(smem), "l"(g));
}

// swizzle for 128B rows: off = row*128 + (colbyte ^ ((row&7)<<4))
__device__ __forceinline__ uint32_t swz_row(uint32_t row, uint32_t colbyte) {
    return row * 128u + (colbyte ^ ((row & 7u) << 4));
}

__device__ __forceinline__ void ldsm_x4(uint32_t (&r)[4], uint32_t addr) {
    asm volatile("ldmatrix.sync.aligned.m8n8.x4.shared.b16 {%0,%1,%2,%3}, [%4];"
                 : "=r"(r[0]), "=r"(r[1]), "=r"(r[2]), "=r"(r[3]) : "r"(addr));
}

__device__ __forceinline__ void mma16816(float (&d)[4], const uint32_t (&a)[4],
                                         const uint32_t (&b)[2]) {
    asm volatile(
        "mma.sync.aligned.m16n8k16.row.col.f32.bf16.bf16.f32 "
        "{%0,%1,%2,%3}, {%4,%5,%6,%7}, {%8,%9}, {%0,%1,%2,%3};"
        : "+f"(d[0]), "+f"(d[1]), "+f"(d[2]), "+f"(d[3])
        : "r"(a[0]), "r"(a[1]), "r"(a[2]), "r"(a[3]), "r"(b[0]), "r"(b[1]));
}

// ------------------------- split kernel: fp32 -> (bf16 hi, bf16 lo) -------------------------
__global__ void moe_split_kernel(const float* __restrict__ src, bf16* __restrict__ hi,
                                 bf16* __restrict__ lo, size_t n8) {
    size_t i = (size_t)blockIdx.x * blockDim.x + threadIdx.x;
    size_t stride = (size_t)gridDim.x * blockDim.x;
    for (; i < n8; i += stride) {
        const float4* s = (const float4*)(src + i * 8);
        float4 a = s[0], b = s[1];
        float v[8] = {a.x, a.y, a.z, a.w, b.x, b.y, b.z, b.w};
        union { bf16 h[8]; uint4 u; } H, L;
        #pragma unroll
        for (int j = 0; j < 8; ++j) {
            bf16 h = __float2bfloat16(v[j]);
            H.h[j] = h;
            L.h[j] = __float2bfloat16(v[j] - __bfloat162float(h));
        }
        *(uint4*)(hi + i * 8) = H.u;
        *(uint4*)(lo + i * 8) = L.u;
    }
}

// ------------------------- router: logits -> softmax -> sort desc -------------------------
__global__ void moe_router_kernel(const float* __restrict__ hs, const float* __restrict__ Wr,
                                  float* __restrict__ probs) {
    int warp = threadIdx.x >> 5, lane = threadIdx.x & 31;
    int n = blockIdx.x * 4 + warp;
    if (n >= NTOK) return;
    const float* x = hs + (size_t)n * HDIM;
    float acc[NEXP];
    #pragma unroll
    for (int e = 0; e < NEXP; ++e) acc[e] = 0.f;
    for (int j = lane; j < HDIM; j += 32) {
        float xv = x[j];
        #pragma unroll
        for (int e = 0; e < NEXP; ++e) acc[e] += xv * Wr[e * HDIM + j];
    }
    #pragma unroll
    for (int off = 16; off; off >>= 1) {
        #pragma unroll
        for (int e = 0; e < NEXP; ++e)
            acc[e] += __shfl_down_sync(0xffffffffu, acc[e], off);
    }
    if (lane == 0) {
        float m = acc[0];
        #pragma unroll
        for (int e = 1; e < NEXP; ++e) m = fmaxf(m, acc[e]);
        float s = 0.f, p[NEXP];
        #pragma unroll
        for (int e = 0; e < NEXP; ++e) { p[e] = expf(acc[e] - m); s += p[e]; }
        float inv = 1.f / s;
        #pragma unroll
        for (int e = 0; e < NEXP; ++e) p[e] *= inv;
        #pragma unroll
        for (int i = 1; i < NEXP; ++i) {
            float key = p[i];
            int j = i - 1;
            while (j >= 0 && p[j] < key) { p[j + 1] = p[j]; --j; }
            p[j + 1] = key;
        }
        #pragma unroll
        for (int e = 0; e < NEXP; ++e) probs[n * NEXP + e] = p[e];
    }
}

// ------------------------- combined-load bf16x3 GEMM -------------------------
// Tile 128x256, 8 warps (2x4 of 64x64 warp tiles), K-chunk 64, double-buffered.
// Per chunk: load Ahi,Alo,Bhi,Blo once; issue 3 phase-MMAs (Ahi*Blo, Ahi*Bhi, Alo*Bhi).
// MODE 0 (GEMM1): per-expert (blockIdx.z); epilogue mid_e = split(prob[m,e]*gelu(D)).
// MODE 1 (GEMM2): single launch; K concatenated over 8 experts; plain fp32 store.
template <int MODE>
__global__ void __launch_bounds__(256, 1) moe_gemm(float* __restrict__ outp) {
    constexpr int MT = 128;
    constexpr int NT = 256;
    constexpr int A_T = MT * 128;            // bytes per A tile (hi or lo)
    constexpr int B_T = NT * 128;            // bytes per B tile
    constexpr int STAGE = 2 * A_T + 2 * B_T; // 98304

    extern __shared__ char dsm[];
    const int tid = threadIdx.x, wid = tid >> 5, lane = tid & 31;
    const int m0 = blockIdx.x * MT;
    const int n0 = blockIdx.y * NT;
    const int ez = blockIdx.z;

    uint32_t tiles = (smem_u32(dsm) + 1023u) & ~1023u;

    const int NCH = (MODE == 0) ? (HDIM / 64) : (NEXP * IDIM / 64);

    auto load_chunk = [&](int c, int b) {
        const bf16 *aH, *aL, *bH, *bL;
        size_t strA, strB;
        int kk;
        if (MODE == 0) {
            kk = c * 64;
            aH = g_x_hi; aL = g_x_lo; strA = HDIM;
            size_t eo = (size_t)ez * IDIM * HDIM;
            bH = g_w1_hi + eo; bL = g_w1_lo + eo; strB = HDIM;
        } else {
            int ec = c >> 6; kk = (c & 63) * 64;
            size_t ao = (size_t)ec * NTOK * IDIM;
            aH = g_mid_hi + ao; aL = g_mid_lo + ao; strA = IDIM;
            size_t eo = (size_t)ec * HDIM * IDIM;
            bH = g_w2_hi + eo; bL = g_w2_lo + eo; strB = IDIM;
        }
        uint32_t sA = tiles + b * STAGE, sAl = sA + A_T;
        uint32_t sB = sA + 2 * A_T, sBl = sB + B_T;
        #pragma unroll
        for (int v = 0; v < MT * 8 / 256; ++v) {
            int idx = v * 256 + tid;
            int r = idx >> 3, c16 = idx & 7;
            uint32_t off = swz_row((uint32_t)r, (uint32_t)(c16 * 16));
            size_t gofs = (size_t)(m0 + r) * strA + kk + c16 * 8;
            cp_async16(sA + off, aH + gofs);
            cp_async16(sAl + off, aL + gofs);
        }
        #pragma unroll
        for (int v = 0; v < NT * 8 / 256; ++v) {
            int idx = v * 256 + tid;
            int r = idx >> 3, c16 = idx & 7;
            uint32_t off = swz_row((uint32_t)r, (uint32_t)(c16 * 16));
            size_t gofs = (size_t)(n0 + r) * strB + kk + c16 * 8;
            cp_async16(sB + off, bH + gofs);
            cp_async16(sBl + off, bL + gofs);
        }
        asm volatile("cp.async.commit_group;\n" ::: "memory");
    };

    const int wm = (wid & 1) * 64;
    const int wn = (wid >> 1) * 64;

    float acc[4][8][4];
    #pragma unroll
    for (int mt = 0; mt < 4; ++mt)
        #pragma unroll
        for (int nt = 0; nt < 8; ++nt)
            #pragma unroll
            for (int q = 0; q < 4; ++q) acc[mt][nt][q] = 0.f;

    const uint32_t rA = (((uint32_t)lane >> 3) & 1u) * 8u + ((uint32_t)lane & 7u);
    const uint32_t kA0 = (((uint32_t)lane >> 4) & 1u) * 16u;
    const uint32_t rB = (((uint32_t)lane >> 4) & 1u) * 8u + ((uint32_t)lane & 7u);
    const uint32_t kB0 = (((uint32_t)lane >> 3) & 1u) * 16u;

    load_chunk(0, 0);
    load_chunk(1, 1);

    for (int c = 0; c < NCH; ++c) {
        int b = c & 1;
        if (c + 1 < NCH) asm volatile("cp.async.wait_group 1;\n" ::: "memory");
        else             asm volatile("cp.async.wait_group 0;\n" ::: "memory");
        __syncthreads();

        uint32_t sA = tiles + b * STAGE, sAl = sA + A_T;
        uint32_t sB = sA + 2 * A_T, sBl = sB + B_T;

        #pragma unroll
        for (int ks = 0; ks < 4; ++ks) {
            uint32_t af[4][4], bfr[8][2];
            // A-hi fragments
            #pragma unroll
            for (int mt = 0; mt < 4; ++mt)
                ldsm_x4(af[mt], sA + swz_row((uint32_t)(wm + mt * 16) + rA,
                                             (uint32_t)(ks * 32) + kA0));
            // B-lo fragments -> phase: Ahi * Blo
            #pragma unroll
            for (int nt2 = 0; nt2 < 4; ++nt2) {
                uint32_t t[4];
                ldsm_x4(t, sBl + swz_row((uint32_t)(wn + nt2 * 16) + rB,
                                         (uint32_t)(ks * 32) + kB0));
                bfr[2 * nt2][0] = t[0]; bfr[2 * nt2][1] = t[1];
                bfr[2 * nt2 + 1][0] = t[2]; bfr[2 * nt2 + 1][1] = t[3];
            }
            #pragma unroll
            for (int mt = 0; mt < 4; ++mt)
                #pragma unroll
                for (int nt = 0; nt < 8; ++nt) mma16816(acc[mt][nt], af[mt], bfr[nt]);
            // B-hi fragments -> phase: Ahi * Bhi
            #pragma unroll
            for (int nt2 = 0; nt2 < 4; ++nt2) {
                uint32_t t[4];
                ldsm_x4(t, sB + swz_row((uint32_t)(wn + nt2 * 16) + rB,
                                        (uint32_t)(ks * 32) + kB0));
                bfr[2 * nt2][0] = t[0]; bfr[2 * nt2][1] = t[1];
                bfr[2 * nt2 + 1][0] = t[2]; bfr[2 * nt2 + 1][1] = t[3];
            }
            #pragma unroll
            for (int mt = 0; mt < 4; ++mt)
                #pragma unroll
                for (int nt = 0; nt < 8; ++nt) mma16816(acc[mt][nt], af[mt], bfr[nt]);
            // A-lo fragments -> phase: Alo * Bhi
            #pragma unroll
            for (int mt = 0; mt < 4; ++mt)
                ldsm_x4(af[mt], sAl + swz_row((uint32_t)(wm + mt * 16) + rA,
                                              (uint32_t)(ks * 32) + kA0));
            #pragma unroll
            for (int mt = 0; mt < 4; ++mt)
                #pragma unroll
                for (int nt = 0; nt < 8; ++nt) mma16816(acc[mt][nt], af[mt], bfr[nt]);
        }

        __syncthreads();
        if (c + 2 < NCH) load_chunk(c + 2, b);
    }

    // ------------------------- epilogue -------------------------
    const int rbase = m0 + wm + (lane >> 2);
    const int cbase = wn + (lane & 3) * 2;   // local col within tile

    if (MODE == 0) {
        #pragma unroll
        for (int mt = 0; mt < 4; ++mt) {
            #pragma unroll
            for (int half = 0; half < 2; ++half) {
                int row = rbase + mt * 16 + half * 8;
                float pw = g_probs[row * NEXP + ez];
                size_t base = ((size_t)ez * NTOK + row) * IDIM + n0;
                #pragma unroll
                for (int nt = 0; nt < 8; ++nt) {
                    int col = cbase + nt * 8;
                    float v0 = acc[mt][nt][half * 2 + 0];
                    float v1 = acc[mt][nt][half * 2 + 1];
                    float g0 = pw * 0.5f * v0 * (1.0f + erff(v0 * 0.70710678118654752f));
                    float g1 = pw * 0.5f * v1 * (1.0f + erff(v1 * 0.70710678118654752f));
                    bf16 h0 = __float2bfloat16(g0), h1 = __float2bfloat16(g1);
                    bf16 l0 = __float2bfloat16(g0 - __bfloat162float(h0));
                    bf16 l1 = __float2bfloat16(g1 - __bfloat162float(h1));
                    *(__nv_bfloat162*)(g_mid_hi + base + col) = __nv_bfloat162(h0, h1);
                    *(__nv_bfloat162*)(g_mid_lo + base + col) = __nv_bfloat162(l0, l1);
                }
            }
        }
    } else {
        #pragma unroll
        for (int mt = 0; mt < 4; ++mt) {
            #pragma unroll
            for (int half = 0; half < 2; ++half) {
                int row = rbase + mt * 16 + half * 8;
                size_t base = (size_t)row * HDIM + n0;
                #pragma unroll
                for (int nt = 0; nt < 8; ++nt) {
                    int col = cbase + nt * 8;
                    float2 v;
                    v.x = acc[mt][nt][half * 2 + 0];
                    v.y = acc[mt][nt][half * 2 + 1];
                    *(float2*)(outp + base + col) = v;
                }
            }
        }
    }
}

// ------------------------- host launch -------------------------
extern "C" void kernel_launch(void* const* d_in, const int* in_sizes, int n_in,
                              void* d_out, int out_size) {
    const float* hs = (const float*)d_in[0];
    const float* Wr = (const float*)d_in[1];
    const float* W1 = (const float*)d_in[2];
    const float* W2 = (const float*)d_in[3];
    float* outp = (float*)d_out;

    void *xh, *xl, *w1h, *w1l, *w2h, *w2l, *pp;
    cudaGetSymbolAddress(&xh, g_x_hi);
    cudaGetSymbolAddress(&xl, g_x_lo);
    cudaGetSymbolAddress(&w1h, g_w1_hi);
    cudaGetSymbolAddress(&w1l, g_w1_lo);
    cudaGetSymbolAddress(&w2h, g_w2_hi);
    cudaGetSymbolAddress(&w2l, g_w2_lo);
    cudaGetSymbolAddress(&pp, g_probs);

    const int SMEM = 1024 + 2 * 98304;   // 197632
    cudaFuncSetAttribute((const void*)moe_gemm<0>,
                         cudaFuncAttributeMaxDynamicSharedMemorySize, SMEM);
    cudaFuncSetAttribute((const void*)moe_gemm<1>,
                         cudaFuncAttributeMaxDynamicSharedMemorySize, SMEM);

    moe_split_kernel<<<2048, 256>>>(hs, (bf16*)xh, (bf16*)xl, (size_t)NTOK * HDIM / 8);
    moe_split_kernel<<<4096, 256>>>(W1, (bf16*)w1h, (bf16*)w1l, (size_t)NEXP * IDIM * HDIM / 8);
    moe_split_kernel<<<4096, 256>>>(W2, (bf16*)w2h, (bf16*)w2l, (size_t)NEXP * HDIM * IDIM / 8);
    moe_router_kernel<<<NTOK / 4, 128>>>(hs, Wr, (float*)pp);

    // GEMM1: all experts, tokens x IDIM, epilogue = prob-scaled gelu, split to mid
    moe_gemm<0><<<dim3(NTOK / 128, IDIM / 256, NEXP), 256, SMEM>>>(nullptr);
    // GEMM2: single GEMM, K concatenated over experts; writes out directly
    moe_gemm<1><<<dim3(NTOK / 128, HDIM / 256, 1), 256, SMEM>>>(outp);
}

// round 5
// speedup vs baseline: 1.3471x; 1.3471x over previous
#include <cuda_runtime.h>
#include <cuda_bf16.h>
#include <cstdint>
#include <cstddef>

#define NTOK 4096
#define HDIM 1024
#define IDIM 4096
#define NEXP 8

typedef __nv_bfloat16 bf16;

// ------------------------- scratch (static device, no allocs) -------------------------
__device__ bf16 g_x_hi[(size_t)NTOK * HDIM];
__device__ bf16 g_x_lo[(size_t)NTOK * HDIM];
__device__ bf16 g_w1_hi[(size_t)NEXP * IDIM * HDIM];
__device__ bf16 g_w1_lo[(size_t)NEXP * IDIM * HDIM];
__device__ bf16 g_w2_hi[(size_t)NEXP * HDIM * IDIM];
__device__ bf16 g_w2_lo[(size_t)NEXP * HDIM * IDIM];
__device__ bf16 g_mid_hi[(size_t)NTOK * IDIM];
__device__ bf16 g_mid_lo[(size_t)NTOK * IDIM];
__device__ float g_probs[NTOK * NEXP];

// ------------------------- PTX helpers -------------------------
__device__ __forceinline__ uint32_t smem_u32(const void* p) {
    uint32_t a;
    asm("{ .reg .u64 t; cvta.to.shared.u64 t, %1; cvt.u32.u64 %0, t; }" : "=r"(a) : "l"(p));
    return a;
}

__device__ __forceinline__ void cp_async16(uint32_t smem, const void* g) {
    asm volatile("cp.async.cg.shared.global [%0], [%1], 16;\n" :: "r"(smem), "l"(g));
}

// swizzle for 128B rows: off = row*128 + (colbyte ^ ((row&7)<<4))
__device__ __forceinline__ uint32_t swz_row(uint32_t row, uint32_t colbyte) {
    return row * 128u + (colbyte ^ ((row & 7u) << 4));
}

__device__ __forceinline__ void ldsm_x4(uint32_t (&r)[4], uint32_t addr) {
    asm volatile("ldmatrix.sync.aligned.m8n8.x4.shared.b16 {%0,%1,%2,%3}, [%4];"
                 : "=r"(r[0]), "=r"(r[1]), "=r"(r[2]), "=r"(r[3]) : "r"(addr));
}

__device__ __forceinline__ void mma16816(float (&d)[4], const uint32_t (&a)[4],
                                         const uint32_t (&b)[2]) {
    asm volatile(
        "mma.sync.aligned.m16n8k16.row.col.f32.bf16.bf16.f32 "
        "{%0,%1,%2,%3}, {%4,%5,%6,%7}, {%8,%9}, {%0,%1,%2,%3};"
        : "+f"(d[0]), "+f"(d[1]), "+f"(d[2]), "+f"(d[3])
        : "r"(a[0]), "r"(a[1]), "r"(a[2]), "r"(a[3]), "r"(b[0]), "r"(b[1]));
}

// ------------------------- split kernel: fp32 -> (bf16 hi, bf16 lo) -------------------------
__global__ void moe_split_kernel(const float* __restrict__ src, bf16* __restrict__ hi,
                                 bf16* __restrict__ lo, size_t n8) {
    size_t i = (size_t)blockIdx.x * blockDim.x + threadIdx.x;
    size_t stride = (size_t)gridDim.x * blockDim.x;
    for (; i < n8; i += stride) {
        const float4* s = (const float4*)(src + i * 8);
        float4 a = s[0], b = s[1];
        float v[8] = {a.x, a.y, a.z, a.w, b.x, b.y, b.z, b.w};
        union { bf16 h[8]; uint4 u; } H, L;
        #pragma unroll
        for (int j = 0; j < 8; ++j) {
            bf16 h = __float2bfloat16(v[j]);
            H.h[j] = h;
            L.h[j] = __float2bfloat16(v[j] - __bfloat162float(h));
        }
        *(uint4*)(hi + i * 8) = H.u;
        *(uint4*)(lo + i * 8) = L.u;
    }
}

// ------------------------- router: logits -> softmax -> sort desc -------------------------
__global__ void moe_router_kernel(const float* __restrict__ hs, const float* __restrict__ Wr,
                                  float* __restrict__ probs) {
    int warp = threadIdx.x >> 5, lane = threadIdx.x & 31;
    int n = blockIdx.x * 4 + warp;
    if (n >= NTOK) return;
    const float* x = hs + (size_t)n * HDIM;
    float acc[NEXP];
    #pragma unroll
    for (int e = 0; e < NEXP; ++e) acc[e] = 0.f;
    for (int j = lane; j < HDIM; j += 32) {
        float xv = x[j];
        #pragma unroll
        for (int e = 0; e < NEXP; ++e) acc[e] += xv * Wr[e * HDIM + j];
    }
    #pragma unroll
    for (int off = 16; off; off >>= 1) {
        #pragma unroll
        for (int e = 0; e < NEXP; ++e)
            acc[e] += __shfl_down_sync(0xffffffffu, acc[e], off);
    }
    if (lane == 0) {
        float m = acc[0];
        #pragma unroll
        for (int e = 1; e < NEXP; ++e) m = fmaxf(m, acc[e]);
        float s = 0.f, p[NEXP];
        #pragma unroll
        for (int e = 0; e < NEXP; ++e) { p[e] = expf(acc[e] - m); s += p[e]; }
        float inv = 1.f / s;
        #pragma unroll
        for (int e = 0; e < NEXP; ++e) p[e] *= inv;
        #pragma unroll
        for (int i = 1; i < NEXP; ++i) {
            float key = p[i];
            int j = i - 1;
            while (j >= 0 && p[j] < key) { p[j + 1] = p[j]; --j; }
            p[j + 1] = key;
        }
        #pragma unroll
        for (int e = 0; e < NEXP; ++e) probs[n * NEXP + e] = p[e];
    }
}

// ------------------------- combined-load bf16x3 GEMM (round-3 skeleton) -------------------
// Tile 128x128, 4 warps (2x2 of 64x64 warp tiles), 2 CTA/SM.
// K-chunk 32 with hi/lo PACKED per 128B smem row: [hi 64B | lo 64B].
// Per chunk: load A-hi/lo + B-hi/lo once; 3 phase sweeps (Ahi*Blo, Ahi*Bhi, Alo*Bhi).
// mode 0: mid = split(gelu(D))   mode 1: out (+)= prob[m,e] * D
__global__ void __launch_bounds__(128, 2) moe_gemm(
    const bf16* __restrict__ Ahi, const bf16* __restrict__ Alo,
    const bf16* __restrict__ Bhi, const bf16* __restrict__ Blo,
    int K, int mode, int eidx,
    bf16* __restrict__ midhi, bf16* __restrict__ midlo,
    float* __restrict__ outp, const float* __restrict__ probs) {
    constexpr int MT = 128;
    constexpr int NT = 128;
    constexpr int A_BYTES = MT * 128;        // packed hi|lo rows, K=32 per chunk
    constexpr int B_BYTES = NT * 128;
    constexpr int STAGE = A_BYTES + B_BYTES; // 32768

    extern __shared__ char dsm[];

    const int tid = threadIdx.x, wid = tid >> 5, lane = tid & 31;
    const int m0 = blockIdx.x * MT;
    const int n0 = blockIdx.y * NT;

    uint32_t tiles = (smem_u32(dsm) + 1023u) & ~1023u;

    const int NCH = K / 32;   // 32-element K chunks (all 3 phases done per chunk)

    auto load_chunk = [&](int c, int b) {
        int kk = c * 32;
        uint32_t sA = tiles + b * STAGE;
        uint32_t sB = sA + A_BYTES;
        // A: 128 rows x 8 col16-slots (slots 0-3 = hi bytes [0,64), 4-7 = lo at +64)
        #pragma unroll
        for (int v = 0; v < 8; ++v) {
            int idx = v * 128 + tid;
            int r = idx >> 3, s = idx & 7;
            const bf16* src = (s < 4) ? Ahi : Alo;
            cp_async16(sA + swz_row((uint32_t)r, (uint32_t)(s * 16)),
                       src + (size_t)(m0 + r) * K + kk + (s & 3) * 8);
        }
        #pragma unroll
        for (int v = 0; v < 8; ++v) {
            int idx = v * 128 + tid;
            int r = idx >> 3, s = idx & 7;
            const bf16* src = (s < 4) ? Bhi : Blo;
            cp_async16(sB + swz_row((uint32_t)r, (uint32_t)(s * 16)),
                       src + (size_t)(n0 + r) * K + kk + (s & 3) * 8);
        }
        asm volatile("cp.async.commit_group;\n" ::: "memory");
    };

    const int wm = (wid & 1) * 64;
    const int wn = (wid >> 1) * 64;

    float acc[4][8][4];
    #pragma unroll
    for (int mt = 0; mt < 4; ++mt)
        #pragma unroll
        for (int nt = 0; nt < 8; ++nt)
            #pragma unroll
            for (int q = 0; q < 4; ++q) acc[mt][nt][q] = 0.f;

    const uint32_t rA = (((uint32_t)lane >> 3) & 1u) * 8u + ((uint32_t)lane & 7u);
    const uint32_t kA0 = (((uint32_t)lane >> 4) & 1u) * 16u;
    const uint32_t rB = (((uint32_t)lane >> 4) & 1u) * 8u + ((uint32_t)lane & 7u);
    const uint32_t kB0 = (((uint32_t)lane >> 3) & 1u) * 16u;

    load_chunk(0, 0);
    load_chunk(1, 1);

    for (int c = 0; c < NCH; ++c) {
        int b = c & 1;
        if (c + 1 < NCH) asm volatile("cp.async.wait_group 1;\n" ::: "memory");
        else             asm volatile("cp.async.wait_group 0;\n" ::: "memory");
        __syncthreads();

        uint32_t sA = tiles + b * STAGE;
        uint32_t sB = sA + A_BYTES;

        #pragma unroll
        for (int ks = 0; ks < 2; ++ks) {
            uint32_t af[4][4], bfr[8][2];
            const uint32_t kbase = (uint32_t)(ks * 32);
            // A-hi fragments (hi half: bytes [0,64))
            #pragma unroll
            for (int mt = 0; mt < 4; ++mt)
                ldsm_x4(af[mt], sA + swz_row((uint32_t)(wm + mt * 16) + rA, kbase + kA0));
            // B-lo fragments (lo half: +64B) -> phase Ahi*Blo
            #pragma unroll
            for (int nt2 = 0; nt2 < 4; ++nt2) {
                uint32_t t[4];
                ldsm_x4(t, sB + swz_row((uint32_t)(wn + nt2 * 16) + rB, 64u + kbase + kB0));
                bfr[2 * nt2][0] = t[0]; bfr[2 * nt2][1] = t[1];
                bfr[2 * nt2 + 1][0] = t[2]; bfr[2 * nt2 + 1][1] = t[3];
            }
            #pragma unroll
            for (int mt = 0; mt < 4; ++mt)
                #pragma unroll
                for (int nt = 0; nt < 8; ++nt) mma16816(acc[mt][nt], af[mt], bfr[nt]);
            // B-hi fragments -> phase Ahi*Bhi
            #pragma unroll
            for (int nt2 = 0; nt2 < 4; ++nt2) {
                uint32_t t[4];
                ldsm_x4(t, sB + swz_row((uint32_t)(wn + nt2 * 16) + rB, kbase + kB0));
                bfr[2 * nt2][0] = t[0]; bfr[2 * nt2][1] = t[1];
                bfr[2 * nt2 + 1][0] = t[2]; bfr[2 * nt2 + 1][1] = t[3];
            }
            #pragma unroll
            for (int mt = 0; mt < 4; ++mt)
                #pragma unroll
                for (int nt = 0; nt < 8; ++nt) mma16816(acc[mt][nt], af[mt], bfr[nt]);
            // A-lo fragments (+64B) -> phase Alo*Bhi
            #pragma unroll
            for (int mt = 0; mt < 4; ++mt)
                ldsm_x4(af[mt], sA + swz_row((uint32_t)(wm + mt * 16) + rA, 64u + kbase + kA0));
            #pragma unroll
            for (int mt = 0; mt < 4; ++mt)
                #pragma unroll
                for (int nt = 0; nt < 8; ++nt) mma16816(acc[mt][nt], af[mt], bfr[nt]);
        }

        __syncthreads();
        if (c + 2 < NCH) load_chunk(c + 2, b);
    }

    // ------------------------- epilogue (identical to round 3) -------------------------
    const int rbase = m0 + wm + (lane >> 2);
    const int cbase = n0 + wn + (lane & 3) * 2;

    if (mode == 0) {
        #pragma unroll
        for (int mt = 0; mt < 4; ++mt) {
            #pragma unroll
            for (int half = 0; half < 2; ++half) {
                int row = rbase + mt * 16 + half * 8;
                size_t base = (size_t)row * IDIM;
                #pragma unroll
                for (int nt = 0; nt < 8; ++nt) {
                    int col = cbase + nt * 8;
                    float v0 = acc[mt][nt][half * 2 + 0];
                    float v1 = acc[mt][nt][half * 2 + 1];
                    float g0 = 0.5f * v0 * (1.0f + erff(v0 * 0.70710678118654752f));
                    float g1 = 0.5f * v1 * (1.0f + erff(v1 * 0.70710678118654752f));
                    bf16 h0 = __float2bfloat16(g0), h1 = __float2bfloat16(g1);
                    bf16 l0 = __float2bfloat16(g0 - __bfloat162float(h0));
                    bf16 l1 = __float2bfloat16(g1 - __bfloat162float(h1));
                    *(__nv_bfloat162*)(midhi + base + col) = __nv_bfloat162(h0, h1);
                    *(__nv_bfloat162*)(midlo + base + col) = __nv_bfloat162(l0, l1);
                }
            }
        }
    } else {
        #pragma unroll
        for (int mt = 0; mt < 4; ++mt) {
            #pragma unroll
            for (int half = 0; half < 2; ++half) {
                int row = rbase + mt * 16 + half * 8;
                float pw = probs[row * NEXP + eidx];
                size_t base = (size_t)row * HDIM;
                #pragma unroll
                for (int nt = 0; nt < 8; ++nt) {
                    int col = cbase + nt * 8;
                    float2 v;
                    v.x = acc[mt][nt][half * 2 + 0] * pw;
                    v.y = acc[mt][nt][half * 2 + 1] * pw;
                    if (eidx > 0) {
                        float2 old = *(float2*)(outp + base + col);
                        v.x += old.x; v.y += old.y;
                    }
                    *(float2*)(outp + base + col) = v;
                }
            }
        }
    }
}

// ------------------------- host launch -------------------------
extern "C" void kernel_launch(void* const* d_in, const int* in_sizes, int n_in,
                              void* d_out, int out_size) {
    const float* hs = (const float*)d_in[0];
    const float* Wr = (const float*)d_in[1];
    const float* W1 = (const float*)d_in[2];
    const float* W2 = (const float*)d_in[3];
    float* outp = (float*)d_out;

    void *xh, *xl, *w1h, *w1l, *w2h, *w2l, *mh, *ml, *pp;
    cudaGetSymbolAddress(&xh, g_x_hi);
    cudaGetSymbolAddress(&xl, g_x_lo);
    cudaGetSymbolAddress(&w1h, g_w1_hi);
    cudaGetSymbolAddress(&w1l, g_w1_lo);
    cudaGetSymbolAddress(&w2h, g_w2_hi);
    cudaGetSymbolAddress(&w2l, g_w2_lo);
    cudaGetSymbolAddress(&mh, g_mid_hi);
    cudaGetSymbolAddress(&ml, g_mid_lo);
    cudaGetSymbolAddress(&pp, g_probs);

    const int SMEM = 1024 + 2 * 32768;   // 66560, 2 CTA/SM
    cudaFuncSetAttribute((const void*)moe_gemm,
                         cudaFuncAttributeMaxDynamicSharedMemorySize, SMEM);

    moe_split_kernel<<<2048, 256>>>(hs, (bf16*)xh, (bf16*)xl, (size_t)NTOK * HDIM / 8);
    moe_split_kernel<<<4096, 256>>>(W1, (bf16*)w1h, (bf16*)w1l, (size_t)NEXP * IDIM * HDIM / 8);
    moe_split_kernel<<<4096, 256>>>(W2, (bf16*)w2h, (bf16*)w2l, (size_t)NEXP * HDIM * IDIM / 8);
    moe_router_kernel<<<NTOK / 4, 128>>>(hs, Wr, (float*)pp);

    for (int e = 0; e < NEXP; ++e) {
        size_t off1 = (size_t)e * IDIM * HDIM;
        size_t off2 = (size_t)e * HDIM * IDIM;
        moe_gemm<<<dim3(NTOK / 128, IDIM / 128), 128, SMEM>>>(
            (const bf16*)xh, (const bf16*)xl,
            (const bf16*)w1h + off1, (const bf16*)w1l + off1,
            HDIM, 0, e,
            (bf16*)mh, (bf16*)ml, nullptr, nullptr);
        moe_gemm<<<dim3(NTOK / 128, HDIM / 128), 128, SMEM>>>(
            (const bf16*)mh, (const bf16*)ml,
            (const bf16*)w2h + off2, (const bf16*)w2l + off2,
            IDIM, 1, e,
            nullptr, nullptr, outp, (const float*)pp);
    }
}

// round 7
// speedup vs baseline: 3.5623x; 2.6444x over previous
#include <cuda_runtime.h>
#include <cuda_fp16.h>
#include <cstdint>
#include <cstddef>

#define NTOK 4096
#define HDIM 1024
#define IDIM 4096
#define NEXP 8

// ------------------------- scratch (static device, no allocs) -------------------------
__device__ __half g_x[(size_t)NTOK * HDIM];
__device__ __half g_w1[(size_t)NEXP * IDIM * HDIM];
__device__ __half g_w2[(size_t)NEXP * HDIM * IDIM];
__device__ __half g_mid[(size_t)NTOK * IDIM];
__device__ float g_probs[NTOK * NEXP];

// ------------------------- PTX helpers -------------------------
__device__ __forceinline__ uint32_t smem_u32(const void* p) {
    uint32_t a;
    asm("{ .reg .u64 t; cvta.to.shared.u64 t, %1; cvt.u32.u64 %0, t; }" : "=r"(a) : "l"(p));
    return a;
}

__device__ __forceinline__ void cp_async16(uint32_t smem, const void* g) {
    asm volatile("cp.async.cg.shared.global [%0], [%1], 16;\n" :: "r"(smem), "l"(g));
}

// swizzle for 128B rows: off = row*128 + (colbyte ^ ((row&7)<<4))
__device__ __forceinline__ uint32_t swz_row(uint32_t row, uint32_t colbyte) {
    return row * 128u + (colbyte ^ ((row & 7u) << 4));
}

__device__ __forceinline__ void ldsm_x4(uint32_t (&r)[4], uint32_t addr) {
    asm volatile("ldmatrix.sync.aligned.m8n8.x4.shared.b16 {%0,%1,%2,%3}, [%4];"
                 : "=r"(r[0]), "=r"(r[1]), "=r"(r[2]), "=r"(r[3]) : "r"(addr));
}

__device__ __forceinline__ void mma16816(float (&d)[4], const uint32_t (&a)[4],
                                         const uint32_t (&b)[2]) {
    asm volatile(
        "mma.sync.aligned.m16n8k16.row.col.f32.f16.f16.f32 "
        "{%0,%1,%2,%3}, {%4,%5,%6,%7}, {%8,%9}, {%0,%1,%2,%3};"
        : "+f"(d[0]), "+f"(d[1]), "+f"(d[2]), "+f"(d[3])
        : "r"(a[0]), "r"(a[1]), "r"(a[2]), "r"(a[3]), "r"(b[0]), "r"(b[1]));
}

// ------------------------- convert kernel: fp32 -> fp16 -------------------------
__global__ void moe_cvt_kernel(const float* __restrict__ src, __half* __restrict__ dst,
                               size_t n8) {
    size_t i = (size_t)blockIdx.x * blockDim.x + threadIdx.x;
    size_t stride = (size_t)gridDim.x * blockDim.x;
    for (; i < n8; i += stride) {
        const float4* s = (const float4*)(src + i * 8);
        float4 a = s[0], b = s[1];
        union { __half h[8]; uint4 u; } H;
        H.h[0] = __float2half_rn(a.x); H.h[1] = __float2half_rn(a.y);
        H.h[2] = __float2half_rn(a.z); H.h[3] = __float2half_rn(a.w);
        H.h[4] = __float2half_rn(b.x); H.h[5] = __float2half_rn(b.y);
        H.h[6] = __float2half_rn(b.z); H.h[7] = __float2half_rn(b.w);
        *(uint4*)(dst + i * 8) = H.u;
    }
}

// ------------------------- router: logits -> softmax -> sort desc -------------------------
__global__ void moe_router_kernel(const float* __restrict__ hs, const float* __restrict__ Wr,
                                  float* __restrict__ probs) {
    int warp = threadIdx.x >> 5, lane = threadIdx.x & 31;
    int n = blockIdx.x * 4 + warp;
    if (n >= NTOK) return;
    const float* x = hs + (size_t)n * HDIM;
    float acc[NEXP];
    #pragma unroll
    for (int e = 0; e < NEXP; ++e) acc[e] = 0.f;
    for (int j = lane; j < HDIM; j += 32) {
        float xv = x[j];
        #pragma unroll
        for (int e = 0; e < NEXP; ++e) acc[e] += xv * Wr[e * HDIM + j];
    }
    #pragma unroll
    for (int off = 16; off; off >>= 1) {
        #pragma unroll
        for (int e = 0; e < NEXP; ++e)
            acc[e] += __shfl_down_sync(0xffffffffu, acc[e], off);
    }
    if (lane == 0) {
        float m = acc[0];
        #pragma unroll
        for (int e = 1; e < NEXP; ++e) m = fmaxf(m, acc[e]);
        float s = 0.f, p[NEXP];
        #pragma unroll
        for (int e = 0; e < NEXP; ++e) { p[e] = expf(acc[e] - m); s += p[e]; }
        float inv = 1.f / s;
        #pragma unroll
        for (int e = 0; e < NEXP; ++e) p[e] *= inv;
        #pragma unroll
        for (int i = 1; i < NEXP; ++i) {
            float key = p[i];
            int j = i - 1;
            while (j >= 0 && p[j] < key) { p[j + 1] = p[j]; --j; }
            p[j + 1] = key;
        }
        #pragma unroll
        for (int e = 0; e < NEXP; ++e) probs[n * NEXP + e] = p[e];
    }
}

// ------------------------- fp16 GEMM (exact round-3 loop, single phase) -----------------
// Tile 128x128, 4 warps (2x2 of 64x64 warp tiles), K-chunk 64, double-buffered, 2 CTA/SM.
// mode 0: mid = fp16(gelu(D))   mode 1: out (+)= prob[m,e] * D
__global__ void __launch_bounds__(128, 2) moe_gemm(
    const __half* __restrict__ A, const __half* __restrict__ B,
    int K, int mode, int eidx,
    __half* __restrict__ mid,
    float* __restrict__ outp, const float* __restrict__ probs) {
    constexpr int MT = 128;
    constexpr int NT = 128;
    constexpr int A_BYTES = MT * 128;
    constexpr int B_BYTES = NT * 128;
    constexpr int STAGE = A_BYTES + B_BYTES;   // 32768

    extern __shared__ char dsm[];

    const int tid = threadIdx.x, wid = tid >> 5, lane = tid & 31;
    const int m0 = blockIdx.x * MT;
    const int n0 = blockIdx.y * NT;

    uint32_t tiles = (smem_u32(dsm) + 1023u) & ~1023u;

    const int NC = K / 64;   // 64-element K chunks, single phase

    auto load_chunk = [&](int c, int b) {
        int kk = c * 64;
        uint32_t sA = tiles + b * STAGE;
        uint32_t sB = sA + A_BYTES;
        #pragma unroll
        for (int v = 0; v < 8; ++v) {
            int idx = v * 128 + tid;
            int r = idx >> 3, c16 = idx & 7;
            cp_async16(sA + swz_row((uint32_t)r, (uint32_t)(c16 * 16)),
                       A + (size_t)(m0 + r) * K + kk + c16 * 8);
        }
        #pragma unroll
        for (int v = 0; v < 8; ++v) {
            int idx = v * 128 + tid;
            int r = idx >> 3, c16 = idx & 7;
            cp_async16(sB + swz_row((uint32_t)r, (uint32_t)(c16 * 16)),
                       B + (size_t)(n0 + r) * K + kk + c16 * 8);
        }
        asm volatile("cp.async.commit_group;\n" ::: "memory");
    };

    const int wm = (wid & 1) * 64;
    const int wn = (wid >> 1) * 64;

    float acc[4][8][4];
    #pragma unroll
    for (int mt = 0; mt < 4; ++mt)
        #pragma unroll
        for (int nt = 0; nt < 8; ++nt)
            #pragma unroll
            for (int q = 0; q < 4; ++q) acc[mt][nt][q] = 0.f;

    const uint32_t rA = (((uint32_t)lane >> 3) & 1u) * 8u + ((uint32_t)lane & 7u);
    const uint32_t kA0 = (((uint32_t)lane >> 4) & 1u) * 16u;
    const uint32_t rB = (((uint32_t)lane >> 4) & 1u) * 8u + ((uint32_t)lane & 7u);
    const uint32_t kB0 = (((uint32_t)lane >> 3) & 1u) * 16u;

    load_chunk(0, 0);
    load_chunk(1, 1);

    for (int c = 0; c < NC; ++c) {
        int b = c & 1;
        if (c + 1 < NC) asm volatile("cp.async.wait_group 1;\n" ::: "memory");
        else            asm volatile("cp.async.wait_group 0;\n" ::: "memory");
        __syncthreads();

        uint32_t sA = tiles + b * STAGE;
        uint32_t sB = sA + A_BYTES;

        #pragma unroll
        for (int ks = 0; ks < 4; ++ks) {
            uint32_t af[4][4];
            #pragma unroll
            for (int mt = 0; mt < 4; ++mt) {
                uint32_t row = (uint32_t)(wm + mt * 16) + rA;
                ldsm_x4(af[mt], sA + swz_row(row, (uint32_t)(ks * 32) + kA0));
            }
            uint32_t bfr[8][2];
            #pragma unroll
            for (int nt2 = 0; nt2 < 4; ++nt2) {
                uint32_t t[4];
                uint32_t row = (uint32_t)(wn + nt2 * 16) + rB;
                ldsm_x4(t, sB + swz_row(row, (uint32_t)(ks * 32) + kB0));
                bfr[2 * nt2][0] = t[0]; bfr[2 * nt2][1] = t[1];
                bfr[2 * nt2 + 1][0] = t[2]; bfr[2 * nt2 + 1][1] = t[3];
            }
            #pragma unroll
            for (int mt = 0; mt < 4; ++mt)
                #pragma unroll
                for (int nt = 0; nt < 8; ++nt)
                    mma16816(acc[mt][nt], af[mt], bfr[nt]);
        }

        __syncthreads();
        if (c + 2 < NC) load_chunk(c + 2, b);
    }

    // ------------------------- epilogue -------------------------
    const int rbase = m0 + wm + (lane >> 2);
    const int cbase = n0 + wn + (lane & 3) * 2;

    if (mode == 0) {
        #pragma unroll
        for (int mt = 0; mt < 4; ++mt) {
            #pragma unroll
            for (int half = 0; half < 2; ++half) {
                int row = rbase + mt * 16 + half * 8;
                size_t base = (size_t)row * IDIM;
                #pragma unroll
                for (int nt = 0; nt < 8; ++nt) {
                    int col = cbase + nt * 8;
                    float v0 = acc[mt][nt][half * 2 + 0];
                    float v1 = acc[mt][nt][half * 2 + 1];
                    float g0 = 0.5f * v0 * (1.0f + erff(v0 * 0.70710678118654752f));
                    float g1 = 0.5f * v1 * (1.0f + erff(v1 * 0.70710678118654752f));
                    __half2 h2;
                    h2.x = __float2half_rn(g0);
                    h2.y = __float2half_rn(g1);
                    *(__half2*)(mid + base + col) = h2;
                }
            }
        }
    } else {
        #pragma unroll
        for (int mt = 0; mt < 4; ++mt) {
            #pragma unroll
            for (int half = 0; half < 2; ++half) {
                int row = rbase + mt * 16 + half * 8;
                float pw = probs[row * NEXP + eidx];
                size_t base = (size_t)row * HDIM;
                #pragma unroll
                for (int nt = 0; nt < 8; ++nt) {
                    int col = cbase + nt * 8;
                    float2 v;
                    v.x = acc[mt][nt][half * 2 + 0] * pw;
                    v.y = acc[mt][nt][half * 2 + 1] * pw;
                    if (eidx > 0) {
                        float2 old = *(float2*)(outp + base + col);
                        v.x += old.x; v.y += old.y;
                    }
                    *(float2*)(outp + base + col) = v;
                }
            }
        }
    }
}

// ------------------------- host launch -------------------------
extern "C" void kernel_launch(void* const* d_in, const int* in_sizes, int n_in,
                              void* d_out, int out_size) {
    const float* hs = (const float*)d_in[0];
    const float* Wr = (const float*)d_in[1];
    const float* W1 = (const float*)d_in[2];
    const float* W2 = (const float*)d_in[3];
    float* outp = (float*)d_out;

    void *xp, *w1p, *w2p, *mp, *pp;
    cudaGetSymbolAddress(&xp, g_x);
    cudaGetSymbolAddress(&w1p, g_w1);
    cudaGetSymbolAddress(&w2p, g_w2);
    cudaGetSymbolAddress(&mp, g_mid);
    cudaGetSymbolAddress(&pp, g_probs);

    const int SMEM = 1024 + 2 * 32768;   // 66560, 2 CTA/SM
    cudaFuncSetAttribute((const void*)moe_gemm,
                         cudaFuncAttributeMaxDynamicSharedMemorySize, SMEM);

    moe_cvt_kernel<<<2048, 256>>>(hs, (__half*)xp, (size_t)NTOK * HDIM / 8);
    moe_cvt_kernel<<<4096, 256>>>(W1, (__half*)w1p, (size_t)NEXP * IDIM * HDIM / 8);
    moe_cvt_kernel<<<4096, 256>>>(W2, (__half*)w2p, (size_t)NEXP * HDIM * IDIM / 8);
    moe_router_kernel<<<NTOK / 4, 128>>>(hs, Wr, (float*)pp);

    for (int e = 0; e < NEXP; ++e) {
        size_t off1 = (size_t)e * IDIM * HDIM;
        size_t off2 = (size_t)e * HDIM * IDIM;
        moe_gemm<<<dim3(NTOK / 128, IDIM / 128), 128, SMEM>>>(
            (const __half*)xp, (const __half*)w1p + off1,
            HDIM, 0, e,
            (__half*)mp, nullptr, nullptr);
        moe_gemm<<<dim3(NTOK / 128, HDIM / 128), 128, SMEM>>>(
            (const __half*)mp, (const __half*)w2p + off2,
            IDIM, 1, e,
            nullptr, outp, (const float*)pp);
    }
}

// round 8
// speedup vs baseline: 4.1567x; 1.1669x over previous
#include <cuda_runtime.h>
#include <cuda_fp16.h>
#include <cstdint>
#include <cstddef>

#define NTOK 4096
#define HDIM 1024
#define IDIM 4096
#define NEXP 8

// ------------------------- scratch (static device, no allocs) -------------------------
__device__ __half g_x[(size_t)NTOK * HDIM];
__device__ __half g_w1[(size_t)NEXP * IDIM * HDIM];
__device__ __half g_w2[(size_t)NEXP * HDIM * IDIM];
__device__ __half g_mid[(size_t)NEXP * NTOK * IDIM];     // per-expert gelu output
__device__ float g_part[(size_t)NEXP * NTOK * HDIM];     // per-expert weighted partials
__device__ float g_probs[NTOK * NEXP];

// ------------------------- PTX helpers -------------------------
__device__ __forceinline__ uint32_t smem_u32(const void* p) {
    uint32_t a;
    asm("{ .reg .u64 t; cvta.to.shared.u64 t, %1; cvt.u32.u64 %0, t; }" : "=r"(a) : "l"(p));
    return a;
}

__device__ __forceinline__ void cp_async16(uint32_t smem, const void* g) {
    asm volatile("cp.async.cg.shared.global [%0], [%1], 16;\n" :: "r"(smem), "l"(g));
}

// swizzle for 128B rows: off = row*128 + (colbyte ^ ((row&7)<<4))
__device__ __forceinline__ uint32_t swz_row(uint32_t row, uint32_t colbyte) {
    return row * 128u + (colbyte ^ ((row & 7u) << 4));
}

__device__ __forceinline__ void ldsm_x4(uint32_t (&r)[4], uint32_t addr) {
    asm volatile("ldmatrix.sync.aligned.m8n8.x4.shared.b16 {%0,%1,%2,%3}, [%4];"
                 : "=r"(r[0]), "=r"(r[1]), "=r"(r[2]), "=r"(r[3]) : "r"(addr));
}

__device__ __forceinline__ void mma16816(float (&d)[4], const uint32_t (&a)[4],
                                         const uint32_t (&b)[2]) {
    asm volatile(
        "mma.sync.aligned.m16n8k16.row.col.f32.f16.f16.f32 "
        "{%0,%1,%2,%3}, {%4,%5,%6,%7}, {%8,%9}, {%0,%1,%2,%3};"
        : "+f"(d[0]), "+f"(d[1]), "+f"(d[2]), "+f"(d[3])
        : "r"(a[0]), "r"(a[1]), "r"(a[2]), "r"(a[3]), "r"(b[0]), "r"(b[1]));
}

// ------------------------- convert kernel: fp32 -> fp16 -------------------------
__global__ void moe_cvt_kernel(const float* __restrict__ src, __half* __restrict__ dst,
                               size_t n8) {
    size_t i = (size_t)blockIdx.x * blockDim.x + threadIdx.x;
    size_t stride = (size_t)gridDim.x * blockDim.x;
    for (; i < n8; i += stride) {
        const float4* s = (const float4*)(src + i * 8);
        float4 a = s[0], b = s[1];
        union { __half h[8]; uint4 u; } H;
        H.h[0] = __float2half_rn(a.x); H.h[1] = __float2half_rn(a.y);
        H.h[2] = __float2half_rn(a.z); H.h[3] = __float2half_rn(a.w);
        H.h[4] = __float2half_rn(b.x); H.h[5] = __float2half_rn(b.y);
        H.h[6] = __float2half_rn(b.z); H.h[7] = __float2half_rn(b.w);
        *(uint4*)(dst + i * 8) = H.u;
    }
}

// ------------------------- router: logits -> softmax -> sort desc -------------------------
__global__ void moe_router_kernel(const float* __restrict__ hs, const float* __restrict__ Wr,
                                  float* __restrict__ probs) {
    int warp = threadIdx.x >> 5, lane = threadIdx.x & 31;
    int n = blockIdx.x * 4 + warp;
    if (n >= NTOK) return;
    const float* x = hs + (size_t)n * HDIM;
    float acc[NEXP];
    #pragma unroll
    for (int e = 0; e < NEXP; ++e) acc[e] = 0.f;
    for (int j = lane; j < HDIM; j += 32) {
        float xv = x[j];
        #pragma unroll
        for (int e = 0; e < NEXP; ++e) acc[e] += xv * Wr[e * HDIM + j];
    }
    #pragma unroll
    for (int off = 16; off; off >>= 1) {
        #pragma unroll
        for (int e = 0; e < NEXP; ++e)
            acc[e] += __shfl_down_sync(0xffffffffu, acc[e], off);
    }
    if (lane == 0) {
        float m = acc[0];
        #pragma unroll
        for (int e = 1; e < NEXP; ++e) m = fmaxf(m, acc[e]);
        float s = 0.f, p[NEXP];
        #pragma unroll
        for (int e = 0; e < NEXP; ++e) { p[e] = expf(acc[e] - m); s += p[e]; }
        float inv = 1.f / s;
        #pragma unroll
        for (int e = 0; e < NEXP; ++e) p[e] *= inv;
        #pragma unroll
        for (int i = 1; i < NEXP; ++i) {
            float key = p[i];
            int j = i - 1;
            while (j >= 0 && p[j] < key) { p[j + 1] = p[j]; --j; }
            p[j + 1] = key;
        }
        #pragma unroll
        for (int e = 0; e < NEXP; ++e) probs[n * NEXP + e] = p[e];
    }
}

// ------------------------- fp16 GEMM, expert-fused via blockIdx.z ------------------------
// Tile 128x128, 4 warps (2x2 of 64x64 warp tiles), K-chunk 64, double-buffered, 2 CTA/SM.
// MODE 0: K=HDIM;  A=x, B=w1[z];  mid[z] = fp16(gelu(D))
// MODE 1: K=IDIM;  A=mid[z], B=w2[z];  part[z] = prob[m,z] * D   (no RMW)
template <int MODE>
__global__ void __launch_bounds__(128, 2) moe_gemm() {
    constexpr int K = (MODE == 0) ? HDIM : IDIM;
    constexpr int MT = 128;
    constexpr int NT = 128;
    constexpr int A_BYTES = MT * 128;
    constexpr int B_BYTES = NT * 128;
    constexpr int STAGE = A_BYTES + B_BYTES;   // 32768
    constexpr int NC = K / 64;

    extern __shared__ char dsm[];

    const int tid = threadIdx.x, wid = tid >> 5, lane = tid & 31;
    const int m0 = blockIdx.x * MT;
    const int n0 = blockIdx.y * NT;
    const int ez = blockIdx.z;

    const __half* A;
    const __half* B;
    if (MODE == 0) {
        A = g_x;
        B = g_w1 + (size_t)ez * IDIM * HDIM;
    } else {
        A = g_mid + (size_t)ez * NTOK * IDIM;
        B = g_w2 + (size_t)ez * HDIM * IDIM;
    }

    uint32_t tiles = (smem_u32(dsm) + 1023u) & ~1023u;

    auto load_chunk = [&](int c, int b) {
        int kk = c * 64;
        uint32_t sA = tiles + b * STAGE;
        uint32_t sB = sA + A_BYTES;
        #pragma unroll
        for (int v = 0; v < 8; ++v) {
            int idx = v * 128 + tid;
            int r = idx >> 3, c16 = idx & 7;
            cp_async16(sA + swz_row((uint32_t)r, (uint32_t)(c16 * 16)),
                       A + (size_t)(m0 + r) * K + kk + c16 * 8);
        }
        #pragma unroll
        for (int v = 0; v < 8; ++v) {
            int idx = v * 128 + tid;
            int r = idx >> 3, c16 = idx & 7;
            cp_async16(sB + swz_row((uint32_t)r, (uint32_t)(c16 * 16)),
                       B + (size_t)(n0 + r) * K + kk + c16 * 8);
        }
        asm volatile("cp.async.commit_group;\n" ::: "memory");
    };

    const int wm = (wid & 1) * 64;
    const int wn = (wid >> 1) * 64;

    float acc[4][8][4];
    #pragma unroll
    for (int mt = 0; mt < 4; ++mt)
        #pragma unroll
        for (int nt = 0; nt < 8; ++nt)
            #pragma unroll
            for (int q = 0; q < 4; ++q) acc[mt][nt][q] = 0.f;

    const uint32_t rA = (((uint32_t)lane >> 3) & 1u) * 8u + ((uint32_t)lane & 7u);
    const uint32_t kA0 = (((uint32_t)lane >> 4) & 1u) * 16u;
    const uint32_t rB = (((uint32_t)lane >> 4) & 1u) * 8u + ((uint32_t)lane & 7u);
    const uint32_t kB0 = (((uint32_t)lane >> 3) & 1u) * 16u;

    load_chunk(0, 0);
    load_chunk(1, 1);

    for (int c = 0; c < NC; ++c) {
        int b = c & 1;
        if (c + 1 < NC) asm volatile("cp.async.wait_group 1;\n" ::: "memory");
        else            asm volatile("cp.async.wait_group 0;\n" ::: "memory");
        __syncthreads();

        uint32_t sA = tiles + b * STAGE;
        uint32_t sB = sA + A_BYTES;

        #pragma unroll
        for (int ks = 0; ks < 4; ++ks) {
            uint32_t af[4][4];
            #pragma unroll
            for (int mt = 0; mt < 4; ++mt) {
                uint32_t row = (uint32_t)(wm + mt * 16) + rA;
                ldsm_x4(af[mt], sA + swz_row(row, (uint32_t)(ks * 32) + kA0));
            }
            uint32_t bfr[8][2];
            #pragma unroll
            for (int nt2 = 0; nt2 < 4; ++nt2) {
                uint32_t t[4];
                uint32_t row = (uint32_t)(wn + nt2 * 16) + rB;
                ldsm_x4(t, sB + swz_row(row, (uint32_t)(ks * 32) + kB0));
                bfr[2 * nt2][0] = t[0]; bfr[2 * nt2][1] = t[1];
                bfr[2 * nt2 + 1][0] = t[2]; bfr[2 * nt2 + 1][1] = t[3];
            }
            #pragma unroll
            for (int mt = 0; mt < 4; ++mt)
                #pragma unroll
                for (int nt = 0; nt < 8; ++nt)
                    mma16816(acc[mt][nt], af[mt], bfr[nt]);
        }

        __syncthreads();
        if (c + 2 < NC) load_chunk(c + 2, b);
    }

    // ------------------------- epilogue -------------------------
    const int rbase = m0 + wm + (lane >> 2);
    const int cbase = n0 + wn + (lane & 3) * 2;

    if (MODE == 0) {
        __half* mid = g_mid + (size_t)ez * NTOK * IDIM;
        #pragma unroll
        for (int mt = 0; mt < 4; ++mt) {
            #pragma unroll
            for (int half = 0; half < 2; ++half) {
                int row = rbase + mt * 16 + half * 8;
                size_t base = (size_t)row * IDIM;
                #pragma unroll
                for (int nt = 0; nt < 8; ++nt) {
                    int col = cbase + nt * 8;
                    float v0 = acc[mt][nt][half * 2 + 0];
                    float v1 = acc[mt][nt][half * 2 + 1];
                    float g0 = 0.5f * v0 * (1.0f + erff(v0 * 0.70710678118654752f));
                    float g1 = 0.5f * v1 * (1.0f + erff(v1 * 0.70710678118654752f));
                    __half2 h2;
                    h2.x = __float2half_rn(g0);
                    h2.y = __float2half_rn(g1);
                    *(__half2*)(mid + base + col) = h2;
                }
            }
        }
    } else {
        float* part = g_part + (size_t)ez * NTOK * HDIM;
        #pragma unroll
        for (int mt = 0; mt < 4; ++mt) {
            #pragma unroll
            for (int half = 0; half < 2; ++half) {
                int row = rbase + mt * 16 + half * 8;
                float pw = g_probs[row * NEXP + ez];
                size_t base = (size_t)row * HDIM;
                #pragma unroll
                for (int nt = 0; nt < 8; ++nt) {
                    int col = cbase + nt * 8;
                    float2 v;
                    v.x = acc[mt][nt][half * 2 + 0] * pw;
                    v.y = acc[mt][nt][half * 2 + 1] * pw;
                    *(float2*)(part + base + col) = v;
                }
            }
        }
    }
}

// ------------------------- reduce: out = sum_e part[e] -------------------------
__global__ void moe_reduce_kernel(float* __restrict__ outp) {
    constexpr size_t N4 = (size_t)NTOK * HDIM / 4;
    size_t i = (size_t)blockIdx.x * blockDim.x + threadIdx.x;
    size_t stride = (size_t)gridDim.x * blockDim.x;
    for (; i < N4; i += stride) {
        const float4* p = (const float4*)g_part + i;
        float4 s = p[0];
        #pragma unroll
        for (int e = 1; e < NEXP; ++e) {
            float4 v = p[(size_t)e * N4];
            s.x += v.x; s.y += v.y; s.z += v.z; s.w += v.w;
        }
        ((float4*)outp)[i] = s;
    }
}

// ------------------------- host launch -------------------------
extern "C" void kernel_launch(void* const* d_in, const int* in_sizes, int n_in,
                              void* d_out, int out_size) {
    const float* hs = (const float*)d_in[0];
    const float* Wr = (const float*)d_in[1];
    const float* W1 = (const float*)d_in[2];
    const float* W2 = (const float*)d_in[3];
    float* outp = (float*)d_out;

    void *xp, *w1p, *w2p, *pp;
    cudaGetSymbolAddress(&xp, g_x);
    cudaGetSymbolAddress(&w1p, g_w1);
    cudaGetSymbolAddress(&w2p, g_w2);
    cudaGetSymbolAddress(&pp, g_probs);

    const int SMEM = 1024 + 2 * 32768;   // 66560, 2 CTA/SM
    cudaFuncSetAttribute((const void*)moe_gemm<0>,
                         cudaFuncAttributeMaxDynamicSharedMemorySize, SMEM);
    cudaFuncSetAttribute((const void*)moe_gemm<1>,
                         cudaFuncAttributeMaxDynamicSharedMemorySize, SMEM);

    moe_cvt_kernel<<<2048, 256>>>(hs, (__half*)xp, (size_t)NTOK * HDIM / 8);
    moe_cvt_kernel<<<4096, 256>>>(W1, (__half*)w1p, (size_t)NEXP * IDIM * HDIM / 8);
    moe_cvt_kernel<<<4096, 256>>>(W2, (__half*)w2p, (size_t)NEXP * HDIM * IDIM / 8);
    moe_router_kernel<<<NTOK / 4, 128>>>(hs, Wr, (float*)pp);

    // GEMM1: all experts in one launch (8192 CTAs = 27.7 waves)
    moe_gemm<0><<<dim3(NTOK / 128, IDIM / 128, NEXP), 128, SMEM>>>();
    // GEMM2: all experts in one launch (2048 CTAs = 6.9 waves), fp32 partials
    moe_gemm<1><<<dim3(NTOK / 128, HDIM / 128, NEXP), 128, SMEM>>>();
    // Final combine
    moe_reduce_kernel<<<2048, 256>>>(outp);
}